// round 14
// baseline (speedup 1.0000x reference)
#include <cuda_runtime.h>
#include <cuda_fp16.h>
#include <math.h>

#define BB 2
#define SS 4096
#define DD 512
#define HH 8
#define HDIM 64

typedef unsigned int u32;

// ---------------------------------------------------------------------------
// helpers
// ---------------------------------------------------------------------------
__device__ __forceinline__ u32 pack_f16(float lo, float hi) {
    u32 r;
    asm("cvt.rn.f16x2.f32 %0, %1, %2;" : "=r"(r) : "f"(hi), "f"(lo));
    return r;
}
__device__ __forceinline__ void unpack_f16(u32 p, float& lo, float& hi) {
    __half2 h = *(__half2*)&p;
    float2 f = __half22float2(h);
    lo = f.x; hi = f.y;
}
__device__ __forceinline__ void mma_f16(float* c, u32 a0, u32 a1, u32 a2, u32 a3,
                                        u32 b0, u32 b1) {
    asm("mma.sync.aligned.m16n8k16.row.col.f32.f16.f16.f32 "
        "{%0,%1,%2,%3}, {%4,%5,%6,%7}, {%8,%9}, {%0,%1,%2,%3};"
        : "+f"(c[0]), "+f"(c[1]), "+f"(c[2]), "+f"(c[3])
        : "r"(a0), "r"(a1), "r"(a2), "r"(a3), "r"(b0), "r"(b1));
}
__device__ __forceinline__ void ldsm4(u32* r, u32 addr) {
    asm volatile("ldmatrix.sync.aligned.m8n8.x4.shared.b16 {%0,%1,%2,%3}, [%4];"
        : "=r"(r[0]), "=r"(r[1]), "=r"(r[2]), "=r"(r[3]) : "r"(addr));
}
__device__ __forceinline__ void ldsm4t(u32* r, u32 addr) {
    asm volatile("ldmatrix.sync.aligned.m8n8.x4.trans.shared.b16 {%0,%1,%2,%3}, [%4];"
        : "=r"(r[0]), "=r"(r[1]), "=r"(r[2]), "=r"(r[3]) : "r"(addr));
}
__device__ __forceinline__ void cpa16(u32 dst, const void* src) {
    asm volatile("cp.async.cg.shared.global [%0], [%1], 16;" :: "r"(dst), "l"(src));
}
#define CP_COMMIT() asm volatile("cp.async.commit_group;")
#define CP_WAIT(n)  asm volatile("cp.async.wait_group %0;" :: "n"(n))

// ---------------------------------------------------------------------------
// Scratch
// ---------------------------------------------------------------------------
__device__ float g_qkv[(size_t)BB * SS * 3 * DD];
__device__ unsigned short g_xhat[(size_t)BB * SS * DD];     // [8192][512]  fp16
__device__ unsigned short g_ohat[(size_t)BB * SS * DD];     // [8192][512]  fp16
__device__ unsigned short g_wqkvT[(size_t)(3 * DD) * DD];   // [1536][512]  fp16
__device__ unsigned short g_woutT[(size_t)DD * DD];         // [512][512]   fp16
__device__ unsigned short g_qhi[(size_t)BB * HH * SS * HDIM];
__device__ unsigned short g_khi[(size_t)BB * HH * SS * HDIM];
__device__ unsigned short g_vhi[(size_t)BB * HH * SS * HDIM];

// ---------------------------------------------------------------------------
// convert f32 -> fp16, row-major, vectorized
// ---------------------------------------------------------------------------
__global__ __launch_bounds__(256)
void convert_f16_kernel(const float* __restrict__ A, __half* __restrict__ Ah) {
    int idx = blockIdx.x * blockDim.x + threadIdx.x;
    float4 t = *(const float4*)(A + (size_t)idx * 4);
    uint2 hw = make_uint2(pack_f16(t.x, t.y), pack_f16(t.z, t.w));
    *(uint2*)(Ah + (size_t)idx * 4) = hw;
}

// ---------------------------------------------------------------------------
// weight transpose: B [512][N] f32 -> Bt [N][512] fp16
// ---------------------------------------------------------------------------
__global__ __launch_bounds__(256)
void wtrans_kernel(const float* __restrict__ B, __half* __restrict__ Bt, int N) {
    __shared__ __half shi[32][36];
    const int k0 = blockIdx.y * 32, n0 = blockIdx.x * 32;
    const int t = threadIdx.x;
    {
        int kk = t >> 3, n4 = (t & 7) * 4;
        float4 v = *(const float4*)(B + (size_t)(k0 + kk) * N + n0 + n4);
        shi[kk][n4 + 0] = __float2half_rn(v.x);
        shi[kk][n4 + 1] = __float2half_rn(v.y);
        shi[kk][n4 + 2] = __float2half_rn(v.z);
        shi[kk][n4 + 3] = __float2half_rn(v.w);
    }
    __syncthreads();
    {
        int nn = t >> 3, k4 = (t & 7) * 4;
        __half2 h01, h23;
        h01.x = shi[k4 + 0][nn]; h01.y = shi[k4 + 1][nn];
        h23.x = shi[k4 + 2][nn]; h23.y = shi[k4 + 3][nn];
        uint2 hw = make_uint2(*(u32*)&h01, *(u32*)&h23);
        *(uint2*)(Bt + (size_t)(n0 + nn) * DD + k0 + k4) = hw;
    }
}

// ---------------------------------------------------------------------------
// fp16 GEMM: C[M][N] f32 = Ahat[M][512] @ Bt[N][512]^T
// 128x128 tile, BK=64, 2-stage ring (flash-style: wait(0) -> sync -> issue
// next -> compute), 73.7KB smem -> 2 CTAs/SM.
// ---------------------------------------------------------------------------
#define GLDK 72
#define GOPB (128 * GLDK * 2)        // 18432 B per operand-stage
#define GEMM_SMEM (4 * GOPB)         // 73728 B

__global__ __launch_bounds__(256, 2)
void gemm_f16_kernel(const __half* __restrict__ A,
                     const __half* __restrict__ Bt,
                     float* __restrict__ C, int N) {
    extern __shared__ char gsm[];
    const u32 base = (u32)__cvta_generic_to_shared(gsm);

    const int tid = threadIdx.x;
    const int lane = tid & 31, w = tid >> 5;
    const int wm = w >> 2, wn = w & 3;
    const int bm = blockIdx.y * 128, bn = blockIdx.x * 128;
    const int lrow = tid >> 3;          // 0..31
    const int lc8 = (tid & 7) * 8;

    float acc[4][4][4];
#pragma unroll
    for (int mi = 0; mi < 4; mi++)
#pragma unroll
        for (int ni = 0; ni < 4; ni++)
#pragma unroll
            for (int e = 0; e < 4; e++) acc[mi][ni][e] = 0.f;

    const int NKT = DD / 64;   // 8

    // prologue: issue stage 0
    {
        const __half* Ag = A + (size_t)bm * DD;
        const __half* Bg = Bt + (size_t)bn * DD;
#pragma unroll
        for (int i = 0; i < 4; i++) {
            int row = lrow + i * 32;
            u32 off = (u32)((row * GLDK + lc8) * 2);
            cpa16(base + off, Ag + (size_t)row * DD + lc8);
            cpa16(base + 2 * GOPB + off, Bg + (size_t)row * DD + lc8);
        }
        CP_COMMIT();
    }

#pragma unroll 1
    for (int kt = 0; kt < NKT; kt++) {
        CP_WAIT(0);                  // stage kt landed (only group outstanding)
        __syncthreads();             // all warps done with stage kt-1 buffers

        if (kt + 1 < NKT) {
            const int s = (kt + 1) & 1;
            const __half* Ag = A + (size_t)bm * DD + (kt + 1) * 64;
            const __half* Bg = Bt + (size_t)bn * DD + (kt + 1) * 64;
#pragma unroll
            for (int i = 0; i < 4; i++) {
                int row = lrow + i * 32;
                u32 off = (u32)((row * GLDK + lc8) * 2);
                cpa16(base + s * GOPB + off, Ag + (size_t)row * DD + lc8);
                cpa16(base + 2 * GOPB + s * GOPB + off, Bg + (size_t)row * DD + lc8);
            }
            CP_COMMIT();
        }

        const int s = kt & 1;
        const u32 Ab = base + s * GOPB;
        const u32 Bb = base + 2 * GOPB + s * GOPB;
        const int lr = lane & 15, lc = (lane >> 4) * 8;
#pragma unroll
        for (int ks = 0; ks < 4; ks++) {
            const int col = ks * 16 + lc;
            u32 a[4][4], b[4][2];
#pragma unroll
            for (int mi = 0; mi < 4; mi++)
                ldsm4(a[mi], Ab + (u32)(((wm * 64 + mi * 16 + lr) * GLDK + col) * 2));
#pragma unroll
            for (int nip = 0; nip < 2; nip++) {
                u32 t[4];
                ldsm4(t, Bb + (u32)(((wn * 32 + nip * 16 + lr) * GLDK + col) * 2));
                b[2 * nip][0] = t[0]; b[2 * nip + 1][0] = t[1];
                b[2 * nip][1] = t[2]; b[2 * nip + 1][1] = t[3];
            }
#pragma unroll
            for (int mi = 0; mi < 4; mi++)
#pragma unroll
                for (int ni = 0; ni < 4; ni++)
                    mma_f16(acc[mi][ni], a[mi][0], a[mi][1], a[mi][2], a[mi][3],
                            b[ni][0], b[ni][1]);
        }
    }

#pragma unroll
    for (int mi = 0; mi < 4; mi++) {
        int r = bm + wm * 64 + mi * 16 + (lane >> 2);
#pragma unroll
        for (int ni = 0; ni < 4; ni++) {
            int c = bn + wn * 32 + ni * 8 + (lane & 3) * 2;
            *(float2*)&C[(size_t)r * N + c] = make_float2(acc[mi][ni][0], acc[mi][ni][1]);
            *(float2*)&C[(size_t)(r + 8) * N + c] = make_float2(acc[mi][ni][2], acc[mi][ni][3]);
        }
    }
}

// ---------------------------------------------------------------------------
// RoPE + head split + fp16 round. Q pre-scaled by 0.125*log2(e) (exp2 domain).
// ---------------------------------------------------------------------------
#define QSCALE (0.125f * 1.4426950408889634f)

__global__ __launch_bounds__(256)
void rope_split_kernel(const float* __restrict__ qkv,
                       __half* __restrict__ Qhi, __half* __restrict__ Khi,
                       __half* __restrict__ Vhi) {
    int idx = blockIdx.x * blockDim.x + threadIdx.x;
    int i = idx & 31;
    int h = (idx >> 5) & 7;
    int s = (idx >> 8) & 4095;
    int b = idx >> 20;

    size_t row = (size_t)b * SS + s;
    const float* p = qkv + row * (3 * DD) + h * HDIM;

    float q1 = p[i],        q2 = p[i + 32];
    float k1 = p[512 + i],  k2 = p[512 + i + 32];
    float v1 = p[1024 + i], v2 = p[1024 + i + 32];

    float invf = 1.0f / powf(10000.0f, (float)i * (1.0f / 32.0f));
    float ang = (float)s * invf;
    float sn, cs;
    sincosf(ang, &sn, &cs);

    float qr1 = (q1 * cs - q2 * sn) * QSCALE;
    float qr2 = (q2 * cs + q1 * sn) * QSCALE;
    float kr1 = k1 * cs - k2 * sn;
    float kr2 = k2 * cs + k1 * sn;

    size_t orow = ((size_t)(b * HH + h) * SS + s) * HDIM;
    Qhi[orow + i]      = __float2half_rn(qr1);
    Qhi[orow + i + 32] = __float2half_rn(qr2);
    Khi[orow + i]      = __float2half_rn(kr1);
    Khi[orow + i + 32] = __float2half_rn(kr2);
    Vhi[orow + i]      = __float2half_rn(v1);
    Vhi[orow + i + 32] = __float2half_rn(v2);
}

// ---------------------------------------------------------------------------
// Flash attention fp16, wq(8) layout, KV tile 128 (two 64-halves computed per
// load -> half the wait/sync events). exp2 softmax; P rounded once to fp16;
// denominator from the same rounded P. Output fp16 to ohat [b][s][h][d].
// smem: Q [128][72] | K [2 stage][128][72] | V same.  92160 B -> 2 CTAs/SM.
// ---------------------------------------------------------------------------
#define FL_LD 72
#define FL_QSZ   (128 * FL_LD * 2)              // 18432 B
#define FL_KSTG  (128 * FL_LD * 2)              // 18432 B per stage (128 rows)
#define FL_HALF  (64 * FL_LD * 2)               // 9216 B (64-row half)
#define FL_SMEM_BYTES (FL_QSZ + 2 * FL_KSTG + 2 * FL_KSTG)   // 92160

__global__ __launch_bounds__(256, 2)
void flashmma_kernel(const __half* __restrict__ Qhi,
                     const __half* __restrict__ Khi, const __half* __restrict__ Vhi,
                     __half* __restrict__ Ohat) {
    extern __shared__ char smraw[];
    const u32 smb = (u32)__cvta_generic_to_shared(smraw);
    const u32 Qb = smb;
    const u32 Kb = smb + FL_QSZ;
    const u32 Vb = Kb + 2 * FL_KSTG;

    const int tid = threadIdx.x, lane = tid & 31, w = tid >> 5;
    const int bh = blockIdx.y;
    const int qt = gridDim.x - 1 - blockIdx.x;
    const int q0 = qt * 128;
    const int b = bh >> 3, h = bh & 7;

    const size_t qoff = ((size_t)bh * SS + q0) * HDIM;
    const size_t koff = (size_t)bh * SS * HDIM;

    const int lrow = tid >> 3;         // 0..31
    const int lc8 = (tid & 7) * 8;
    const int lr = lane & 15, lc = (lane >> 4) * 8;

    // ---- issue Q + KV tile 0 (128 rows) as one group ----
#pragma unroll
    for (int i = 0; i < 4; i++) {
        int row = lrow + i * 32;       // 0..127
        u32 off = (u32)((row * FL_LD + lc8) * 2);
        cpa16(Qb + off, Qhi + qoff + (size_t)row * HDIM + lc8);
        cpa16(Kb + off, Khi + koff + (size_t)row * HDIM + lc8);
        cpa16(Vb + off, Vhi + koff + (size_t)row * HDIM + lc8);
    }
    CP_COMMIT();

    float oacc[8][4];
#pragma unroll
    for (int nj = 0; nj < 8; nj++)
#pragma unroll
        for (int e = 0; e < 4; e++) oacc[nj][e] = 0.f;
    float lsum[2] = {0.f, 0.f};

    u32 aq[4][4];                      // hoisted Q fragments [ks][4]

    const int jmax = qt;               // KV tiles of 128 rows
#pragma unroll 1
    for (int j = 0; j <= jmax; j++) {
        CP_WAIT(0);
        __syncthreads();

        if (j == 0) {
            // load loop-invariant Q fragments once (16 q-rows per warp)
#pragma unroll
            for (int ks = 0; ks < 4; ks++)
                ldsm4(aq[ks],
                      Qb + (u32)(((w * 16 + lr) * FL_LD + ks * 16 + lc) * 2));
        }

        if (j < jmax) {
            const int s = (j + 1) & 1;
            const size_t kvg = koff + (size_t)((j + 1) * 128) * HDIM;
#pragma unroll
            for (int i = 0; i < 4; i++) {
                int row = lrow + i * 32;
                u32 off = (u32)((row * FL_LD + lc8) * 2);
                cpa16(Kb + s * FL_KSTG + off, Khi + kvg + (size_t)row * HDIM + lc8);
                cpa16(Vb + s * FL_KSTG + off, Vhi + kvg + (size_t)row * HDIM + lc8);
            }
            CP_COMMIT();
        }

        const int s = j & 1;
        const int rg = q0 + w * 16 + (lane >> 2);

#pragma unroll
        for (int half = 0; half < 2; half++) {
            const u32 khb = Kb + s * FL_KSTG + half * FL_HALF;
            const u32 vhb = Vb + s * FL_KSTG + half * FL_HALF;
            const int kv0 = j * 128 + half * 64;

            // ---- S(16x64) = Qh Kh, single pass ----
            float sacc[8][4];
#pragma unroll
            for (int ni = 0; ni < 8; ni++)
#pragma unroll
                for (int e = 0; e < 4; e++) sacc[ni][e] = 0.f;
#pragma unroll
            for (int ks = 0; ks < 4; ks++) {
                const int col = ks * 16 + lc;
                u32 bhr[8][2];
#pragma unroll
                for (int nip = 0; nip < 4; nip++) {
                    u32 ro = (u32)(((nip * 16 + lr) * FL_LD + col) * 2);
                    u32 t[4];
                    ldsm4(t, khb + ro);
                    bhr[2 * nip][0] = t[0]; bhr[2 * nip + 1][0] = t[1];
                    bhr[2 * nip][1] = t[2]; bhr[2 * nip + 1][1] = t[3];
                }
#pragma unroll
                for (int ni = 0; ni < 8; ni++)
                    mma_f16(sacc[ni], aq[ks][0], aq[ks][1], aq[ks][2], aq[ks][3],
                            bhr[ni][0], bhr[ni][1]);
            }

            // ---- exp2, mask, pack to fp16 once; l from the rounded values ----
            const bool diag = (kv0 + 63 > q0);
            u32 aP[4][4];
#pragma unroll
            for (int ni = 0; ni < 8; ni++) {
                const int cg = kv0 + ni * 8 + (lane & 3) * 2;
                float e0 = exp2f(sacc[ni][0]);
                float e1 = exp2f(sacc[ni][1]);
                float e2 = exp2f(sacc[ni][2]);
                float e3 = exp2f(sacc[ni][3]);
                if (diag) {
                    if (cg > rg) e0 = 0.f;
                    if (cg + 1 > rg) e1 = 0.f;
                    if (cg > rg + 8) e2 = 0.f;
                    if (cg + 1 > rg + 8) e3 = 0.f;
                }
                u32 p01 = pack_f16(e0, e1);
                u32 p23 = pack_f16(e2, e3);
                float f0, f1, f2, f3;
                unpack_f16(p01, f0, f1);
                unpack_f16(p23, f2, f3);
                lsum[0] += f0 + f1;
                lsum[1] += f2 + f3;
                const int kc = ni >> 1, hf = (ni & 1) * 2;
                aP[kc][hf]     = p01;
                aP[kc][hf + 1] = p23;
            }

            // ---- O(16x64) += P V ----
#pragma unroll
            for (int kc = 0; kc < 4; kc++) {
                const u32 rowoff = (u32)((kc * 16 + lr) * FL_LD + lc);
                u32 vfr[4][4];
#pragma unroll
                for (int njp = 0; njp < 4; njp++)
                    ldsm4t(vfr[njp], vhb + (rowoff + (u32)(njp * 16)) * 2);
#pragma unroll
                for (int njp = 0; njp < 4; njp++) {
                    mma_f16(oacc[2 * njp], aP[kc][0], aP[kc][1],
                            aP[kc][2], aP[kc][3], vfr[njp][0], vfr[njp][1]);
                    mma_f16(oacc[2 * njp + 1], aP[kc][0], aP[kc][1],
                            aP[kc][2], aP[kc][3], vfr[njp][2], vfr[njp][3]);
                }
            }
        }
    }

    // ---- epilogue: k entirely within warp -> quad reduce only ----
    float l0 = lsum[0], l1 = lsum[1];
    l0 += __shfl_xor_sync(0xffffffffu, l0, 1);
    l0 += __shfl_xor_sync(0xffffffffu, l0, 2);
    l1 += __shfl_xor_sync(0xffffffffu, l1, 1);
    l1 += __shfl_xor_sync(0xffffffffu, l1, 2);
    const float inv0 = 1.0f / l0, inv1 = 1.0f / l1;

    const int r0 = q0 + w * 16 + (lane >> 2);
    __half* dst0 = Ohat + (((size_t)b * SS + r0) * HH + h) * HDIM + (lane & 3) * 2;
    __half* dst1 = dst0 + (size_t)8 * HH * HDIM;
#pragma unroll
    for (int nj = 0; nj < 8; nj++) {
        *(u32*)(dst0 + nj * 8) = pack_f16(oacc[nj][0] * inv0, oacc[nj][1] * inv0);
        *(u32*)(dst1 + nj * 8) = pack_f16(oacc[nj][2] * inv1, oacc[nj][3] * inv1);
    }
}

// ---------------------------------------------------------------------------
// kernel_launch
// ---------------------------------------------------------------------------
extern "C" void kernel_launch(void* const* d_in, const int* in_sizes, int n_in,
                              void* d_out, int out_size) {
    const float* x    = (const float*)d_in[0];
    const float* Wqkv = (const float*)d_in[1];
    const float* Wout = (const float*)d_in[2];
    float* out = (float*)d_out;

    float *qkv;
    __half *xhat, *ohat, *wqkvT, *woutT;
    __half *qhi, *khi, *vhi;
    cudaGetSymbolAddress((void**)&qkv, g_qkv);
    cudaGetSymbolAddress((void**)&xhat, g_xhat);
    cudaGetSymbolAddress((void**)&ohat, g_ohat);
    cudaGetSymbolAddress((void**)&wqkvT, g_wqkvT);
    cudaGetSymbolAddress((void**)&woutT, g_woutT);
    cudaGetSymbolAddress((void**)&qhi, g_qhi);
    cudaGetSymbolAddress((void**)&khi, g_khi);
    cudaGetSymbolAddress((void**)&vhi, g_vhi);

    const int M = BB * SS;   // 8192

    // operand prep
    convert_f16_kernel<<<M * 128 / 256, 256>>>(x, xhat);
    wtrans_kernel<<<dim3(1536 / 32, 512 / 32), 256>>>(Wqkv, wqkvT, 1536);
    wtrans_kernel<<<dim3(512 / 32, 512 / 32), 256>>>(Wout, woutT, 512);

    // 1) QKV projection (single-pass fp16, K=512, 2 CTAs/SM)
    cudaFuncSetAttribute(gemm_f16_kernel, cudaFuncAttributeMaxDynamicSharedMemorySize,
                         GEMM_SMEM);
    gemm_f16_kernel<<<dim3(1536 / 128, M / 128), 256, GEMM_SMEM>>>(xhat, wqkvT, qkv, 1536);

    // 2) RoPE + head split + fp16 round (Q scaled into log2 domain)
    rope_split_kernel<<<BB * SS * HH * 32 / 256, 256>>>(qkv, qhi, khi, vhi);

    // 3) flash attention (wq(8), KV tile 128, 2 CTAs/SM)
    cudaFuncSetAttribute(flashmma_kernel, cudaFuncAttributeMaxDynamicSharedMemorySize,
                         FL_SMEM_BYTES);
    flashmma_kernel<<<dim3(SS / 128, BB * HH), 256, FL_SMEM_BYTES>>>(qhi, khi, vhi, ohat);

    // 4) output projection (single-pass fp16, K=512, 2 CTAs/SM)
    gemm_f16_kernel<<<dim3(512 / 128, M / 128), 256, GEMM_SMEM>>>(ohat, woutT, out, 512);
}

// round 15
// speedup vs baseline: 1.0356x; 1.0356x over previous
#include <cuda_runtime.h>
#include <cuda_fp16.h>
#include <math.h>

#define BB 2
#define SS 4096
#define DD 512
#define HH 8
#define HDIM 64

typedef unsigned int u32;

// ---------------------------------------------------------------------------
// helpers
// ---------------------------------------------------------------------------
__device__ __forceinline__ u32 pack_f16(float lo, float hi) {
    u32 r;
    asm("cvt.rn.f16x2.f32 %0, %1, %2;" : "=r"(r) : "f"(hi), "f"(lo));
    return r;
}
__device__ __forceinline__ void unpack_f16(u32 p, float& lo, float& hi) {
    __half2 h = *(__half2*)&p;
    float2 f = __half22float2(h);
    lo = f.x; hi = f.y;
}
__device__ __forceinline__ void mma_f16(float* c, u32 a0, u32 a1, u32 a2, u32 a3,
                                        u32 b0, u32 b1) {
    asm("mma.sync.aligned.m16n8k16.row.col.f32.f16.f16.f32 "
        "{%0,%1,%2,%3}, {%4,%5,%6,%7}, {%8,%9}, {%0,%1,%2,%3};"
        : "+f"(c[0]), "+f"(c[1]), "+f"(c[2]), "+f"(c[3])
        : "r"(a0), "r"(a1), "r"(a2), "r"(a3), "r"(b0), "r"(b1));
}
__device__ __forceinline__ void ldsm4(u32* r, u32 addr) {
    asm volatile("ldmatrix.sync.aligned.m8n8.x4.shared.b16 {%0,%1,%2,%3}, [%4];"
        : "=r"(r[0]), "=r"(r[1]), "=r"(r[2]), "=r"(r[3]) : "r"(addr));
}
__device__ __forceinline__ void ldsm4t(u32* r, u32 addr) {
    asm volatile("ldmatrix.sync.aligned.m8n8.x4.trans.shared.b16 {%0,%1,%2,%3}, [%4];"
        : "=r"(r[0]), "=r"(r[1]), "=r"(r[2]), "=r"(r[3]) : "r"(addr));
}
__device__ __forceinline__ void cpa16(u32 dst, const void* src) {
    asm volatile("cp.async.cg.shared.global [%0], [%1], 16;" :: "r"(dst), "l"(src));
}
#define CP_COMMIT() asm volatile("cp.async.commit_group;")
#define CP_WAIT(n)  asm volatile("cp.async.wait_group %0;" :: "n"(n))

#define QSCALE (0.125f * 1.4426950408889634f)

// ---------------------------------------------------------------------------
// Scratch
// ---------------------------------------------------------------------------
__device__ unsigned short g_xhat[(size_t)BB * SS * DD];     // [8192][512]  fp16
__device__ unsigned short g_ohat[(size_t)BB * SS * DD];     // [8192][512]  fp16
__device__ unsigned short g_wqkvT[(size_t)(3 * DD) * DD];   // [1536][512]  fp16
__device__ unsigned short g_woutT[(size_t)DD * DD];         // [512][512]   fp16
__device__ unsigned short g_qhi[(size_t)BB * HH * SS * HDIM];
__device__ unsigned short g_khi[(size_t)BB * HH * SS * HDIM];
__device__ unsigned short g_vhi[(size_t)BB * HH * SS * HDIM];

// ---------------------------------------------------------------------------
// convert f32 -> fp16, row-major, vectorized
// ---------------------------------------------------------------------------
__global__ __launch_bounds__(256)
void convert_f16_kernel(const float* __restrict__ A, __half* __restrict__ Ah) {
    int idx = blockIdx.x * blockDim.x + threadIdx.x;
    float4 t = *(const float4*)(A + (size_t)idx * 4);
    uint2 hw = make_uint2(pack_f16(t.x, t.y), pack_f16(t.z, t.w));
    *(uint2*)(Ah + (size_t)idx * 4) = hw;
}

// ---------------------------------------------------------------------------
// weight transpose: B [512][N] f32 -> Bt [N][512] fp16
// ---------------------------------------------------------------------------
__global__ __launch_bounds__(256)
void wtrans_kernel(const float* __restrict__ B, __half* __restrict__ Bt, int N) {
    __shared__ __half shi[32][36];
    const int k0 = blockIdx.y * 32, n0 = blockIdx.x * 32;
    const int t = threadIdx.x;
    {
        int kk = t >> 3, n4 = (t & 7) * 4;
        float4 v = *(const float4*)(B + (size_t)(k0 + kk) * N + n0 + n4);
        shi[kk][n4 + 0] = __float2half_rn(v.x);
        shi[kk][n4 + 1] = __float2half_rn(v.y);
        shi[kk][n4 + 2] = __float2half_rn(v.z);
        shi[kk][n4 + 3] = __float2half_rn(v.w);
    }
    __syncthreads();
    {
        int nn = t >> 3, k4 = (t & 7) * 4;
        __half2 h01, h23;
        h01.x = shi[k4 + 0][nn]; h01.y = shi[k4 + 1][nn];
        h23.x = shi[k4 + 2][nn]; h23.y = shi[k4 + 3][nn];
        uint2 hw = make_uint2(*(u32*)&h01, *(u32*)&h23);
        *(uint2*)(Bt + (size_t)(n0 + nn) * DD + k0 + k4) = hw;
    }
}

// ---------------------------------------------------------------------------
// GEMM mainloop (shared by both GEMM kernels): BK=64, 2-stage ring.
// Computes acc[4][4][4] for this thread's warp tile.
// ---------------------------------------------------------------------------
#define GLDK 72
#define GOPB (128 * GLDK * 2)        // 18432 B per operand-stage
#define GEMM_SMEM (4 * GOPB)         // 73728 B

__device__ __forceinline__ void gemm_mainloop(
    const __half* __restrict__ A, const __half* __restrict__ Bt,
    u32 base, int bm, int bn, int tid, float acc[4][4][4]) {
    const int lane = tid & 31, w = tid >> 5;
    const int wm = w >> 2, wn = w & 3;
    const int lrow = tid >> 3;
    const int lc8 = (tid & 7) * 8;

#pragma unroll
    for (int mi = 0; mi < 4; mi++)
#pragma unroll
        for (int ni = 0; ni < 4; ni++)
#pragma unroll
            for (int e = 0; e < 4; e++) acc[mi][ni][e] = 0.f;

    const int NKT = DD / 64;   // 8

    {
        const __half* Ag = A + (size_t)bm * DD;
        const __half* Bg = Bt + (size_t)bn * DD;
#pragma unroll
        for (int i = 0; i < 4; i++) {
            int row = lrow + i * 32;
            u32 off = (u32)((row * GLDK + lc8) * 2);
            cpa16(base + off, Ag + (size_t)row * DD + lc8);
            cpa16(base + 2 * GOPB + off, Bg + (size_t)row * DD + lc8);
        }
        CP_COMMIT();
    }

#pragma unroll 1
    for (int kt = 0; kt < NKT; kt++) {
        CP_WAIT(0);
        __syncthreads();

        if (kt + 1 < NKT) {
            const int s = (kt + 1) & 1;
            const __half* Ag = A + (size_t)bm * DD + (kt + 1) * 64;
            const __half* Bg = Bt + (size_t)bn * DD + (kt + 1) * 64;
#pragma unroll
            for (int i = 0; i < 4; i++) {
                int row = lrow + i * 32;
                u32 off = (u32)((row * GLDK + lc8) * 2);
                cpa16(base + s * GOPB + off, Ag + (size_t)row * DD + lc8);
                cpa16(base + 2 * GOPB + s * GOPB + off, Bg + (size_t)row * DD + lc8);
            }
            CP_COMMIT();
        }

        const int s = kt & 1;
        const u32 Ab = base + s * GOPB;
        const u32 Bb = base + 2 * GOPB + s * GOPB;
        const int lr = lane & 15, lc = (lane >> 4) * 8;
#pragma unroll
        for (int ks = 0; ks < 4; ks++) {
            const int col = ks * 16 + lc;
            u32 a[4][4], b[4][2];
#pragma unroll
            for (int mi = 0; mi < 4; mi++)
                ldsm4(a[mi], Ab + (u32)(((wm * 64 + mi * 16 + lr) * GLDK + col) * 2));
#pragma unroll
            for (int nip = 0; nip < 2; nip++) {
                u32 t[4];
                ldsm4(t, Bb + (u32)(((wn * 32 + nip * 16 + lr) * GLDK + col) * 2));
                b[2 * nip][0] = t[0]; b[2 * nip + 1][0] = t[1];
                b[2 * nip][1] = t[2]; b[2 * nip + 1][1] = t[3];
            }
#pragma unroll
            for (int mi = 0; mi < 4; mi++)
#pragma unroll
                for (int ni = 0; ni < 4; ni++)
                    mma_f16(acc[mi][ni], a[mi][0], a[mi][1], a[mi][2], a[mi][3],
                            b[ni][0], b[ni][1]);
        }
    }
}

// ---------------------------------------------------------------------------
// out-projection GEMM: f32 C output (final result)
// ---------------------------------------------------------------------------
__global__ __launch_bounds__(256, 2)
void gemm_f16_kernel(const __half* __restrict__ A,
                     const __half* __restrict__ Bt,
                     float* __restrict__ C, int N) {
    extern __shared__ char gsm[];
    const u32 base = (u32)__cvta_generic_to_shared(gsm);
    const int tid = threadIdx.x;
    const int lane = tid & 31, w = tid >> 5;
    const int wm = w >> 2, wn = w & 3;
    const int bm = blockIdx.y * 128, bn = blockIdx.x * 128;

    float acc[4][4][4];
    gemm_mainloop(A, Bt, base, bm, bn, tid, acc);

#pragma unroll
    for (int mi = 0; mi < 4; mi++) {
        int r = bm + wm * 64 + mi * 16 + (lane >> 2);
#pragma unroll
        for (int ni = 0; ni < 4; ni++) {
            int c = bn + wn * 32 + ni * 8 + (lane & 3) * 2;
            *(float2*)&C[(size_t)r * N + c] = make_float2(acc[mi][ni][0], acc[mi][ni][1]);
            *(float2*)&C[(size_t)(r + 8) * N + c] = make_float2(acc[mi][ni][2], acc[mi][ni][3]);
        }
    }
}

// ---------------------------------------------------------------------------
// QKV GEMM with fused RoPE + head-split + fp16 epilogue.
// Tile 128x128; each tile lies entirely in the q, k, or v region (regions are
// 512-wide, tiles 128-aligned). Stage acc in smem (f32, stride 132), then
// cooperatively apply RoPE pairs (i, i+32) and store fp16 in flash layout.
// ---------------------------------------------------------------------------
#define CF_LD 132

__global__ __launch_bounds__(256, 2)
void gemm_qkv_kernel(const __half* __restrict__ A,
                     const __half* __restrict__ Bt,
                     __half* __restrict__ Qhi, __half* __restrict__ Khi,
                     __half* __restrict__ Vhi) {
    extern __shared__ char gsm[];
    const u32 base = (u32)__cvta_generic_to_shared(gsm);
    float* Cf = (float*)gsm;                 // [128][132] = 67584 B (< 73728)
    const int tid = threadIdx.x;
    const int lane = tid & 31, w = tid >> 5;
    const int wm = w >> 2, wn = w & 3;
    const int bm = blockIdx.y * 128, bn = blockIdx.x * 128;

    float acc[4][4][4];
    gemm_mainloop(A, Bt, base, bm, bn, tid, acc);

    // stage accumulator tile in smem (pipeline buffers are dead now)
    __syncthreads();
#pragma unroll
    for (int mi = 0; mi < 4; mi++) {
        int r = wm * 64 + mi * 16 + (lane >> 2);
#pragma unroll
        for (int ni = 0; ni < 4; ni++) {
            int c = wn * 32 + ni * 8 + (lane & 3) * 2;
            *(float2*)&Cf[r * CF_LD + c] = make_float2(acc[mi][ni][0], acc[mi][ni][1]);
            *(float2*)&Cf[(r + 8) * CF_LD + c] = make_float2(acc[mi][ni][2], acc[mi][ni][3]);
        }
    }
    __syncthreads();

    // region: 0 = q, 1 = k, 2 = v ; tile covers heads h0, h0+1 of that region
    const int region = bn >> 9;              // bn / 512
    const int h0 = (bn & 511) >> 6;          // first head in tile
    const int pc = tid & 63;                 // pair-column: hh = pc>>5, ii = pc&31
    const int hh = pc >> 5, ii = pc & 31;
    const int hq = h0 + hh;

    const float invf = 1.0f / powf(10000.0f, (float)ii * (1.0f / 32.0f));

#pragma unroll 1
    for (int row = tid >> 6; row < 128; row += 4) {
        const int gr = bm + row;
        const int s = gr & (SS - 1);
        const int b = gr >> 12;
        const float v1 = Cf[row * CF_LD + hh * 64 + ii];
        const float v2 = Cf[row * CF_LD + hh * 64 + ii + 32];
        const size_t orow = ((size_t)(b * HH + hq) * SS + s) * HDIM;

        if (region == 2) {
            Vhi[orow + ii]      = __float2half_rn(v1);
            Vhi[orow + ii + 32] = __float2half_rn(v2);
        } else {
            float sn, cs;
            sincosf((float)s * invf, &sn, &cs);
            float r1 = v1 * cs - v2 * sn;
            float r2 = v2 * cs + v1 * sn;
            if (region == 0) {
                r1 *= QSCALE; r2 *= QSCALE;
                Qhi[orow + ii]      = __float2half_rn(r1);
                Qhi[orow + ii + 32] = __float2half_rn(r2);
            } else {
                Khi[orow + ii]      = __float2half_rn(r1);
                Khi[orow + ii + 32] = __float2half_rn(r2);
            }
        }
    }
}

// ---------------------------------------------------------------------------
// Flash attention fp16, wq(8) layout, KV tile 128, 2 CTAs/SM.
// exp2 softmax; P rounded once to fp16; denominator from the same rounded P.
// smem: Q [128][72] | K [2 stage][128][72] | V same.  92160 B.
// ---------------------------------------------------------------------------
#define FL_LD 72
#define FL_QSZ   (128 * FL_LD * 2)
#define FL_KSTG  (128 * FL_LD * 2)
#define FL_HALF  (64 * FL_LD * 2)
#define FL_SMEM_BYTES (FL_QSZ + 2 * FL_KSTG + 2 * FL_KSTG)   // 92160

__global__ __launch_bounds__(256, 2)
void flashmma_kernel(const __half* __restrict__ Qhi,
                     const __half* __restrict__ Khi, const __half* __restrict__ Vhi,
                     __half* __restrict__ Ohat) {
    extern __shared__ char smraw[];
    const u32 smb = (u32)__cvta_generic_to_shared(smraw);
    const u32 Qb = smb;
    const u32 Kb = smb + FL_QSZ;
    const u32 Vb = Kb + 2 * FL_KSTG;

    const int tid = threadIdx.x, lane = tid & 31, w = tid >> 5;
    const int bh = blockIdx.y;
    const int qt = gridDim.x - 1 - blockIdx.x;
    const int q0 = qt * 128;
    const int b = bh >> 3, h = bh & 7;

    const size_t qoff = ((size_t)bh * SS + q0) * HDIM;
    const size_t koff = (size_t)bh * SS * HDIM;

    const int lrow = tid >> 3;
    const int lc8 = (tid & 7) * 8;
    const int lr = lane & 15, lc = (lane >> 4) * 8;

#pragma unroll
    for (int i = 0; i < 4; i++) {
        int row = lrow + i * 32;
        u32 off = (u32)((row * FL_LD + lc8) * 2);
        cpa16(Qb + off, Qhi + qoff + (size_t)row * HDIM + lc8);
        cpa16(Kb + off, Khi + koff + (size_t)row * HDIM + lc8);
        cpa16(Vb + off, Vhi + koff + (size_t)row * HDIM + lc8);
    }
    CP_COMMIT();

    float oacc[8][4];
#pragma unroll
    for (int nj = 0; nj < 8; nj++)
#pragma unroll
        for (int e = 0; e < 4; e++) oacc[nj][e] = 0.f;
    float lsum[2] = {0.f, 0.f};

    u32 aq[4][4];

    const int jmax = qt;
#pragma unroll 1
    for (int j = 0; j <= jmax; j++) {
        CP_WAIT(0);
        __syncthreads();

        if (j == 0) {
#pragma unroll
            for (int ks = 0; ks < 4; ks++)
                ldsm4(aq[ks],
                      Qb + (u32)(((w * 16 + lr) * FL_LD + ks * 16 + lc) * 2));
        }

        if (j < jmax) {
            const int s = (j + 1) & 1;
            const size_t kvg = koff + (size_t)((j + 1) * 128) * HDIM;
#pragma unroll
            for (int i = 0; i < 4; i++) {
                int row = lrow + i * 32;
                u32 off = (u32)((row * FL_LD + lc8) * 2);
                cpa16(Kb + s * FL_KSTG + off, Khi + kvg + (size_t)row * HDIM + lc8);
                cpa16(Vb + s * FL_KSTG + off, Vhi + kvg + (size_t)row * HDIM + lc8);
            }
            CP_COMMIT();
        }

        const int s = j & 1;
        const int rg = q0 + w * 16 + (lane >> 2);

#pragma unroll
        for (int half = 0; half < 2; half++) {
            const u32 khb = Kb + s * FL_KSTG + half * FL_HALF;
            const u32 vhb = Vb + s * FL_KSTG + half * FL_HALF;
            const int kv0 = j * 128 + half * 64;

            float sacc[8][4];
#pragma unroll
            for (int ni = 0; ni < 8; ni++)
#pragma unroll
                for (int e = 0; e < 4; e++) sacc[ni][e] = 0.f;
#pragma unroll
            for (int ks = 0; ks < 4; ks++) {
                const int col = ks * 16 + lc;
                u32 bhr[8][2];
#pragma unroll
                for (int nip = 0; nip < 4; nip++) {
                    u32 ro = (u32)(((nip * 16 + lr) * FL_LD + col) * 2);
                    u32 t[4];
                    ldsm4(t, khb + ro);
                    bhr[2 * nip][0] = t[0]; bhr[2 * nip + 1][0] = t[1];
                    bhr[2 * nip][1] = t[2]; bhr[2 * nip + 1][1] = t[3];
                }
#pragma unroll
                for (int ni = 0; ni < 8; ni++)
                    mma_f16(sacc[ni], aq[ks][0], aq[ks][1], aq[ks][2], aq[ks][3],
                            bhr[ni][0], bhr[ni][1]);
            }

            const bool diag = (kv0 + 63 > q0);
            u32 aP[4][4];
#pragma unroll
            for (int ni = 0; ni < 8; ni++) {
                const int cg = kv0 + ni * 8 + (lane & 3) * 2;
                float e0 = exp2f(sacc[ni][0]);
                float e1 = exp2f(sacc[ni][1]);
                float e2 = exp2f(sacc[ni][2]);
                float e3 = exp2f(sacc[ni][3]);
                if (diag) {
                    if (cg > rg) e0 = 0.f;
                    if (cg + 1 > rg) e1 = 0.f;
                    if (cg > rg + 8) e2 = 0.f;
                    if (cg + 1 > rg + 8) e3 = 0.f;
                }
                u32 p01 = pack_f16(e0, e1);
                u32 p23 = pack_f16(e2, e3);
                float f0, f1, f2, f3;
                unpack_f16(p01, f0, f1);
                unpack_f16(p23, f2, f3);
                lsum[0] += f0 + f1;
                lsum[1] += f2 + f3;
                const int kc = ni >> 1, hf = (ni & 1) * 2;
                aP[kc][hf]     = p01;
                aP[kc][hf + 1] = p23;
            }

#pragma unroll
            for (int kc = 0; kc < 4; kc++) {
                const u32 rowoff = (u32)((kc * 16 + lr) * FL_LD + lc);
                u32 vfr[4][4];
#pragma unroll
                for (int njp = 0; njp < 4; njp++)
                    ldsm4t(vfr[njp], vhb + (rowoff + (u32)(njp * 16)) * 2);
#pragma unroll
                for (int njp = 0; njp < 4; njp++) {
                    mma_f16(oacc[2 * njp], aP[kc][0], aP[kc][1],
                            aP[kc][2], aP[kc][3], vfr[njp][0], vfr[njp][1]);
                    mma_f16(oacc[2 * njp + 1], aP[kc][0], aP[kc][1],
                            aP[kc][2], aP[kc][3], vfr[njp][2], vfr[njp][3]);
                }
            }
        }
    }

    float l0 = lsum[0], l1 = lsum[1];
    l0 += __shfl_xor_sync(0xffffffffu, l0, 1);
    l0 += __shfl_xor_sync(0xffffffffu, l0, 2);
    l1 += __shfl_xor_sync(0xffffffffu, l1, 1);
    l1 += __shfl_xor_sync(0xffffffffu, l1, 2);
    const float inv0 = 1.0f / l0, inv1 = 1.0f / l1;

    const int r0 = q0 + w * 16 + (lane >> 2);
    __half* dst0 = Ohat + (((size_t)b * SS + r0) * HH + h) * HDIM + (lane & 3) * 2;
    __half* dst1 = dst0 + (size_t)8 * HH * HDIM;
#pragma unroll
    for (int nj = 0; nj < 8; nj++) {
        *(u32*)(dst0 + nj * 8) = pack_f16(oacc[nj][0] * inv0, oacc[nj][1] * inv0);
        *(u32*)(dst1 + nj * 8) = pack_f16(oacc[nj][2] * inv1, oacc[nj][3] * inv1);
    }
}

// ---------------------------------------------------------------------------
// kernel_launch
// ---------------------------------------------------------------------------
extern "C" void kernel_launch(void* const* d_in, const int* in_sizes, int n_in,
                              void* d_out, int out_size) {
    const float* x    = (const float*)d_in[0];
    const float* Wqkv = (const float*)d_in[1];
    const float* Wout = (const float*)d_in[2];
    float* out = (float*)d_out;

    __half *xhat, *ohat, *wqkvT, *woutT;
    __half *qhi, *khi, *vhi;
    cudaGetSymbolAddress((void**)&xhat, g_xhat);
    cudaGetSymbolAddress((void**)&ohat, g_ohat);
    cudaGetSymbolAddress((void**)&wqkvT, g_wqkvT);
    cudaGetSymbolAddress((void**)&woutT, g_woutT);
    cudaGetSymbolAddress((void**)&qhi, g_qhi);
    cudaGetSymbolAddress((void**)&khi, g_khi);
    cudaGetSymbolAddress((void**)&vhi, g_vhi);

    const int M = BB * SS;   // 8192

    // operand prep
    convert_f16_kernel<<<M * 128 / 256, 256>>>(x, xhat);
    wtrans_kernel<<<dim3(1536 / 32, 512 / 32), 256>>>(Wqkv, wqkvT, 1536);
    wtrans_kernel<<<dim3(512 / 32, 512 / 32), 256>>>(Wout, woutT, 512);

    // 1) QKV projection + fused RoPE/head-split/fp16 epilogue
    cudaFuncSetAttribute(gemm_qkv_kernel, cudaFuncAttributeMaxDynamicSharedMemorySize,
                         GEMM_SMEM);
    gemm_qkv_kernel<<<dim3(1536 / 128, M / 128), 256, GEMM_SMEM>>>(
        xhat, wqkvT, qhi, khi, vhi);

    // 2) flash attention (wq(8), KV tile 128, 2 CTAs/SM)
    cudaFuncSetAttribute(flashmma_kernel, cudaFuncAttributeMaxDynamicSharedMemorySize,
                         FL_SMEM_BYTES);
    flashmma_kernel<<<dim3(SS / 128, BB * HH), 256, FL_SMEM_BYTES>>>(qhi, khi, vhi, ohat);

    // 3) output projection (single-pass fp16, K=512, 2 CTAs/SM)
    cudaFuncSetAttribute(gemm_f16_kernel, cudaFuncAttributeMaxDynamicSharedMemorySize,
                         GEMM_SMEM);
    gemm_f16_kernel<<<dim3(512 / 128, M / 128), 256, GEMM_SMEM>>>(ohat, woutT, out, 512);
}

// round 16
// speedup vs baseline: 1.0433x; 1.0074x over previous
#include <cuda_runtime.h>
#include <cuda_fp16.h>
#include <math.h>

#define BB 2
#define SS 4096
#define DD 512
#define HH 8
#define HDIM 64

typedef unsigned int u32;

// ---------------------------------------------------------------------------
// helpers
// ---------------------------------------------------------------------------
__device__ __forceinline__ u32 pack_f16(float lo, float hi) {
    u32 r;
    asm("cvt.rn.f16x2.f32 %0, %1, %2;" : "=r"(r) : "f"(hi), "f"(lo));
    return r;
}
__device__ __forceinline__ void unpack_f16(u32 p, float& lo, float& hi) {
    __half2 h = *(__half2*)&p;
    float2 f = __half22float2(h);
    lo = f.x; hi = f.y;
}
__device__ __forceinline__ void mma_f16(float* c, u32 a0, u32 a1, u32 a2, u32 a3,
                                        u32 b0, u32 b1) {
    asm("mma.sync.aligned.m16n8k16.row.col.f32.f16.f16.f32 "
        "{%0,%1,%2,%3}, {%4,%5,%6,%7}, {%8,%9}, {%0,%1,%2,%3};"
        : "+f"(c[0]), "+f"(c[1]), "+f"(c[2]), "+f"(c[3])
        : "r"(a0), "r"(a1), "r"(a2), "r"(a3), "r"(b0), "r"(b1));
}
__device__ __forceinline__ void ldsm4(u32* r, u32 addr) {
    asm volatile("ldmatrix.sync.aligned.m8n8.x4.shared.b16 {%0,%1,%2,%3}, [%4];"
        : "=r"(r[0]), "=r"(r[1]), "=r"(r[2]), "=r"(r[3]) : "r"(addr));
}
__device__ __forceinline__ void ldsm4t(u32* r, u32 addr) {
    asm volatile("ldmatrix.sync.aligned.m8n8.x4.trans.shared.b16 {%0,%1,%2,%3}, [%4];"
        : "=r"(r[0]), "=r"(r[1]), "=r"(r[2]), "=r"(r[3]) : "r"(addr));
}
__device__ __forceinline__ void cpa16(u32 dst, const void* src) {
    asm volatile("cp.async.cg.shared.global [%0], [%1], 16;" :: "r"(dst), "l"(src));
}
#define CP_COMMIT() asm volatile("cp.async.commit_group;")
#define CP_WAIT(n)  asm volatile("cp.async.wait_group %0;" :: "n"(n))

#define QSCALE (0.125f * 1.4426950408889634f)

// ---------------------------------------------------------------------------
// Scratch
// ---------------------------------------------------------------------------
__device__ unsigned short g_xhat[(size_t)BB * SS * DD];     // [8192][512]  fp16
__device__ unsigned short g_ohat[(size_t)BB * SS * DD];     // [8192][512]  fp16
__device__ unsigned short g_wqkvT[(size_t)(3 * DD) * DD];   // [1536][512]  fp16
__device__ unsigned short g_woutT[(size_t)DD * DD];         // [512][512]   fp16
__device__ unsigned short g_qhi[(size_t)BB * HH * SS * HDIM];
__device__ unsigned short g_khi[(size_t)BB * HH * SS * HDIM];
__device__ unsigned short g_vhi[(size_t)BB * HH * SS * HDIM];
__device__ float2 g_rope[(size_t)SS * 32];                  // [4096][32] (cos,sin)

// ---------------------------------------------------------------------------
// RoPE table: identical fp32 powf/sincosf pipeline as before (bitwise-same)
// ---------------------------------------------------------------------------
__global__ __launch_bounds__(256)
void rope_table_kernel() {
    int idx = blockIdx.x * blockDim.x + threadIdx.x;   // SS*32
    int i = idx & 31, s = idx >> 5;
    float invf = 1.0f / powf(10000.0f, (float)i * (1.0f / 32.0f));
    float sn, cs;
    sincosf((float)s * invf, &sn, &cs);
    g_rope[idx] = make_float2(cs, sn);
}

// ---------------------------------------------------------------------------
// convert f32 -> fp16, row-major, vectorized
// ---------------------------------------------------------------------------
__global__ __launch_bounds__(256)
void convert_f16_kernel(const float* __restrict__ A, __half* __restrict__ Ah) {
    int idx = blockIdx.x * blockDim.x + threadIdx.x;
    float4 t = *(const float4*)(A + (size_t)idx * 4);
    uint2 hw = make_uint2(pack_f16(t.x, t.y), pack_f16(t.z, t.w));
    *(uint2*)(Ah + (size_t)idx * 4) = hw;
}

// ---------------------------------------------------------------------------
// weight transpose: B [512][N] f32 -> Bt [N][512] fp16
// ---------------------------------------------------------------------------
__global__ __launch_bounds__(256)
void wtrans_kernel(const float* __restrict__ B, __half* __restrict__ Bt, int N) {
    __shared__ __half shi[32][36];
    const int k0 = blockIdx.y * 32, n0 = blockIdx.x * 32;
    const int t = threadIdx.x;
    {
        int kk = t >> 3, n4 = (t & 7) * 4;
        float4 v = *(const float4*)(B + (size_t)(k0 + kk) * N + n0 + n4);
        shi[kk][n4 + 0] = __float2half_rn(v.x);
        shi[kk][n4 + 1] = __float2half_rn(v.y);
        shi[kk][n4 + 2] = __float2half_rn(v.z);
        shi[kk][n4 + 3] = __float2half_rn(v.w);
    }
    __syncthreads();
    {
        int nn = t >> 3, k4 = (t & 7) * 4;
        __half2 h01, h23;
        h01.x = shi[k4 + 0][nn]; h01.y = shi[k4 + 1][nn];
        h23.x = shi[k4 + 2][nn]; h23.y = shi[k4 + 3][nn];
        uint2 hw = make_uint2(*(u32*)&h01, *(u32*)&h23);
        *(uint2*)(Bt + (size_t)(n0 + nn) * DD + k0 + k4) = hw;
    }
}

// ---------------------------------------------------------------------------
// GEMM mainloop (shared): BK=64, 2-stage ring.
// ---------------------------------------------------------------------------
#define GLDK 72
#define GOPB (128 * GLDK * 2)        // 18432 B per operand-stage
#define GEMM_SMEM (4 * GOPB)         // 73728 B

__device__ __forceinline__ void gemm_mainloop(
    const __half* __restrict__ A, const __half* __restrict__ Bt,
    u32 base, int bm, int bn, int tid, float acc[4][4][4]) {
    const int lane = tid & 31, w = tid >> 5;
    const int wm = w >> 2, wn = w & 3;
    const int lrow = tid >> 3;
    const int lc8 = (tid & 7) * 8;

#pragma unroll
    for (int mi = 0; mi < 4; mi++)
#pragma unroll
        for (int ni = 0; ni < 4; ni++)
#pragma unroll
            for (int e = 0; e < 4; e++) acc[mi][ni][e] = 0.f;

    const int NKT = DD / 64;   // 8

    {
        const __half* Ag = A + (size_t)bm * DD;
        const __half* Bg = Bt + (size_t)bn * DD;
#pragma unroll
        for (int i = 0; i < 4; i++) {
            int row = lrow + i * 32;
            u32 off = (u32)((row * GLDK + lc8) * 2);
            cpa16(base + off, Ag + (size_t)row * DD + lc8);
            cpa16(base + 2 * GOPB + off, Bg + (size_t)row * DD + lc8);
        }
        CP_COMMIT();
    }

#pragma unroll 1
    for (int kt = 0; kt < NKT; kt++) {
        CP_WAIT(0);
        __syncthreads();

        if (kt + 1 < NKT) {
            const int s = (kt + 1) & 1;
            const __half* Ag = A + (size_t)bm * DD + (kt + 1) * 64;
            const __half* Bg = Bt + (size_t)bn * DD + (kt + 1) * 64;
#pragma unroll
            for (int i = 0; i < 4; i++) {
                int row = lrow + i * 32;
                u32 off = (u32)((row * GLDK + lc8) * 2);
                cpa16(base + s * GOPB + off, Ag + (size_t)row * DD + lc8);
                cpa16(base + 2 * GOPB + s * GOPB + off, Bg + (size_t)row * DD + lc8);
            }
            CP_COMMIT();
        }

        const int s = kt & 1;
        const u32 Ab = base + s * GOPB;
        const u32 Bb = base + 2 * GOPB + s * GOPB;
        const int lr = lane & 15, lc = (lane >> 4) * 8;
#pragma unroll
        for (int ks = 0; ks < 4; ks++) {
            const int col = ks * 16 + lc;
            u32 a[4][4], b[4][2];
#pragma unroll
            for (int mi = 0; mi < 4; mi++)
                ldsm4(a[mi], Ab + (u32)(((wm * 64 + mi * 16 + lr) * GLDK + col) * 2));
#pragma unroll
            for (int nip = 0; nip < 2; nip++) {
                u32 t[4];
                ldsm4(t, Bb + (u32)(((wn * 32 + nip * 16 + lr) * GLDK + col) * 2));
                b[2 * nip][0] = t[0]; b[2 * nip + 1][0] = t[1];
                b[2 * nip][1] = t[2]; b[2 * nip + 1][1] = t[3];
            }
#pragma unroll
            for (int mi = 0; mi < 4; mi++)
#pragma unroll
                for (int ni = 0; ni < 4; ni++)
                    mma_f16(acc[mi][ni], a[mi][0], a[mi][1], a[mi][2], a[mi][3],
                            b[ni][0], b[ni][1]);
        }
    }
}

// ---------------------------------------------------------------------------
// out-projection GEMM: f32 C output (final result)
// ---------------------------------------------------------------------------
__global__ __launch_bounds__(256, 2)
void gemm_f16_kernel(const __half* __restrict__ A,
                     const __half* __restrict__ Bt,
                     float* __restrict__ C, int N) {
    extern __shared__ char gsm[];
    const u32 base = (u32)__cvta_generic_to_shared(gsm);
    const int tid = threadIdx.x;
    const int lane = tid & 31, w = tid >> 5;
    const int wm = w >> 2, wn = w & 3;
    const int bm = blockIdx.y * 128, bn = blockIdx.x * 128;

    float acc[4][4][4];
    gemm_mainloop(A, Bt, base, bm, bn, tid, acc);

#pragma unroll
    for (int mi = 0; mi < 4; mi++) {
        int r = bm + wm * 64 + mi * 16 + (lane >> 2);
#pragma unroll
        for (int ni = 0; ni < 4; ni++) {
            int c = bn + wn * 32 + ni * 8 + (lane & 3) * 2;
            *(float2*)&C[(size_t)r * N + c] = make_float2(acc[mi][ni][0], acc[mi][ni][1]);
            *(float2*)&C[(size_t)(r + 8) * N + c] = make_float2(acc[mi][ni][2], acc[mi][ni][3]);
        }
    }
}

// ---------------------------------------------------------------------------
// QKV GEMM with fused RoPE (table-driven) + head-split + fp16 epilogue.
// Each thread handles an adjacent ii-pair -> float2 smem loads, u32 stores.
// ---------------------------------------------------------------------------
#define CF_LD 132

__global__ __launch_bounds__(256, 2)
void gemm_qkv_kernel(const __half* __restrict__ A,
                     const __half* __restrict__ Bt,
                     __half* __restrict__ Qhi, __half* __restrict__ Khi,
                     __half* __restrict__ Vhi) {
    extern __shared__ char gsm[];
    const u32 base = (u32)__cvta_generic_to_shared(gsm);
    float* Cf = (float*)gsm;                 // [128][132] = 67584 B (< 73728)
    const int tid = threadIdx.x;
    const int lane = tid & 31, w = tid >> 5;
    const int wm = w >> 2, wn = w & 3;
    const int bm = blockIdx.y * 128, bn = blockIdx.x * 128;

    float acc[4][4][4];
    gemm_mainloop(A, Bt, base, bm, bn, tid, acc);

    // stage accumulator tile in smem (pipeline buffers are dead now)
    __syncthreads();
#pragma unroll
    for (int mi = 0; mi < 4; mi++) {
        int r = wm * 64 + mi * 16 + (lane >> 2);
#pragma unroll
        for (int ni = 0; ni < 4; ni++) {
            int c = wn * 32 + ni * 8 + (lane & 3) * 2;
            *(float2*)&Cf[r * CF_LD + c] = make_float2(acc[mi][ni][0], acc[mi][ni][1]);
            *(float2*)&Cf[(r + 8) * CF_LD + c] = make_float2(acc[mi][ni][2], acc[mi][ni][3]);
        }
    }
    __syncthreads();

    // region: 0 = q, 1 = k, 2 = v ; tile covers heads h0, h0+1 of that region
    const int region = bn >> 9;              // bn / 512
    const int h0 = (bn & 511) >> 6;
    const int pc = tid & 31;                 // hh = pc>>4, ii pair = (pc&15)*2
    const int hh = pc >> 4;
    const int ii = (pc & 15) * 2;
    const int hq = h0 + hh;

#pragma unroll 1
    for (int row = tid >> 5; row < 128; row += 8) {
        const int gr = bm + row;
        const int s = gr & (SS - 1);
        const int b = gr >> 12;
        const float2 v1 = *(const float2*)&Cf[row * CF_LD + hh * 64 + ii];
        const float2 v2 = *(const float2*)&Cf[row * CF_LD + hh * 64 + ii + 32];
        const size_t orow = ((size_t)(b * HH + hq) * SS + s) * HDIM;

        if (region == 2) {
            *(u32*)&Vhi[orow + ii]      = pack_f16(v1.x, v1.y);
            *(u32*)&Vhi[orow + ii + 32] = pack_f16(v2.x, v2.y);
        } else {
            const float2 ta = g_rope[s * 32 + ii];
            const float2 tb = g_rope[s * 32 + ii + 1];
            float r1a = v1.x * ta.x - v2.x * ta.y;
            float r1b = v1.y * tb.x - v2.y * tb.y;
            float r2a = v2.x * ta.x + v1.x * ta.y;
            float r2b = v2.y * tb.x + v1.y * tb.y;
            if (region == 0) {
                r1a *= QSCALE; r1b *= QSCALE; r2a *= QSCALE; r2b *= QSCALE;
                *(u32*)&Qhi[orow + ii]      = pack_f16(r1a, r1b);
                *(u32*)&Qhi[orow + ii + 32] = pack_f16(r2a, r2b);
            } else {
                *(u32*)&Khi[orow + ii]      = pack_f16(r1a, r1b);
                *(u32*)&Khi[orow + ii + 32] = pack_f16(r2a, r2b);
            }
        }
    }
}

// ---------------------------------------------------------------------------
// Flash attention fp16, wq(8) layout, KV tile 128, 2 CTAs/SM.
// ---------------------------------------------------------------------------
#define FL_LD 72
#define FL_QSZ   (128 * FL_LD * 2)
#define FL_KSTG  (128 * FL_LD * 2)
#define FL_HALF  (64 * FL_LD * 2)
#define FL_SMEM_BYTES (FL_QSZ + 2 * FL_KSTG + 2 * FL_KSTG)   // 92160

__global__ __launch_bounds__(256, 2)
void flashmma_kernel(const __half* __restrict__ Qhi,
                     const __half* __restrict__ Khi, const __half* __restrict__ Vhi,
                     __half* __restrict__ Ohat) {
    extern __shared__ char smraw[];
    const u32 smb = (u32)__cvta_generic_to_shared(smraw);
    const u32 Qb = smb;
    const u32 Kb = smb + FL_QSZ;
    const u32 Vb = Kb + 2 * FL_KSTG;

    const int tid = threadIdx.x, lane = tid & 31, w = tid >> 5;
    const int bh = blockIdx.y;
    const int qt = gridDim.x - 1 - blockIdx.x;
    const int q0 = qt * 128;
    const int b = bh >> 3, h = bh & 7;

    const size_t qoff = ((size_t)bh * SS + q0) * HDIM;
    const size_t koff = (size_t)bh * SS * HDIM;

    const int lrow = tid >> 3;
    const int lc8 = (tid & 7) * 8;
    const int lr = lane & 15, lc = (lane >> 4) * 8;

#pragma unroll
    for (int i = 0; i < 4; i++) {
        int row = lrow + i * 32;
        u32 off = (u32)((row * FL_LD + lc8) * 2);
        cpa16(Qb + off, Qhi + qoff + (size_t)row * HDIM + lc8);
        cpa16(Kb + off, Khi + koff + (size_t)row * HDIM + lc8);
        cpa16(Vb + off, Vhi + koff + (size_t)row * HDIM + lc8);
    }
    CP_COMMIT();

    float oacc[8][4];
#pragma unroll
    for (int nj = 0; nj < 8; nj++)
#pragma unroll
        for (int e = 0; e < 4; e++) oacc[nj][e] = 0.f;
    float lsum[2] = {0.f, 0.f};

    u32 aq[4][4];

    const int jmax = qt;
#pragma unroll 1
    for (int j = 0; j <= jmax; j++) {
        CP_WAIT(0);
        __syncthreads();

        if (j == 0) {
#pragma unroll
            for (int ks = 0; ks < 4; ks++)
                ldsm4(aq[ks],
                      Qb + (u32)(((w * 16 + lr) * FL_LD + ks * 16 + lc) * 2));
        }

        if (j < jmax) {
            const int s = (j + 1) & 1;
            const size_t kvg = koff + (size_t)((j + 1) * 128) * HDIM;
#pragma unroll
            for (int i = 0; i < 4; i++) {
                int row = lrow + i * 32;
                u32 off = (u32)((row * FL_LD + lc8) * 2);
                cpa16(Kb + s * FL_KSTG + off, Khi + kvg + (size_t)row * HDIM + lc8);
                cpa16(Vb + s * FL_KSTG + off, Vhi + kvg + (size_t)row * HDIM + lc8);
            }
            CP_COMMIT();
        }

        const int s = j & 1;
        const int rg = q0 + w * 16 + (lane >> 2);

#pragma unroll
        for (int half = 0; half < 2; half++) {
            const u32 khb = Kb + s * FL_KSTG + half * FL_HALF;
            const u32 vhb = Vb + s * FL_KSTG + half * FL_HALF;
            const int kv0 = j * 128 + half * 64;

            float sacc[8][4];
#pragma unroll
            for (int ni = 0; ni < 8; ni++)
#pragma unroll
                for (int e = 0; e < 4; e++) sacc[ni][e] = 0.f;
#pragma unroll
            for (int ks = 0; ks < 4; ks++) {
                const int col = ks * 16 + lc;
                u32 bhr[8][2];
#pragma unroll
                for (int nip = 0; nip < 4; nip++) {
                    u32 ro = (u32)(((nip * 16 + lr) * FL_LD + col) * 2);
                    u32 t[4];
                    ldsm4(t, khb + ro);
                    bhr[2 * nip][0] = t[0]; bhr[2 * nip + 1][0] = t[1];
                    bhr[2 * nip][1] = t[2]; bhr[2 * nip + 1][1] = t[3];
                }
#pragma unroll
                for (int ni = 0; ni < 8; ni++)
                    mma_f16(sacc[ni], aq[ks][0], aq[ks][1], aq[ks][2], aq[ks][3],
                            bhr[ni][0], bhr[ni][1]);
            }

            const bool diag = (kv0 + 63 > q0);
            u32 aP[4][4];
#pragma unroll
            for (int ni = 0; ni < 8; ni++) {
                const int cg = kv0 + ni * 8 + (lane & 3) * 2;
                float e0 = exp2f(sacc[ni][0]);
                float e1 = exp2f(sacc[ni][1]);
                float e2 = exp2f(sacc[ni][2]);
                float e3 = exp2f(sacc[ni][3]);
                if (diag) {
                    if (cg > rg) e0 = 0.f;
                    if (cg + 1 > rg) e1 = 0.f;
                    if (cg > rg + 8) e2 = 0.f;
                    if (cg + 1 > rg + 8) e3 = 0.f;
                }
                u32 p01 = pack_f16(e0, e1);
                u32 p23 = pack_f16(e2, e3);
                float f0, f1, f2, f3;
                unpack_f16(p01, f0, f1);
                unpack_f16(p23, f2, f3);
                lsum[0] += f0 + f1;
                lsum[1] += f2 + f3;
                const int kc = ni >> 1, hf = (ni & 1) * 2;
                aP[kc][hf]     = p01;
                aP[kc][hf + 1] = p23;
            }

#pragma unroll
            for (int kc = 0; kc < 4; kc++) {
                const u32 rowoff = (u32)((kc * 16 + lr) * FL_LD + lc);
                u32 vfr[4][4];
#pragma unroll
                for (int njp = 0; njp < 4; njp++)
                    ldsm4t(vfr[njp], vhb + (rowoff + (u32)(njp * 16)) * 2);
#pragma unroll
                for (int njp = 0; njp < 4; njp++) {
                    mma_f16(oacc[2 * njp], aP[kc][0], aP[kc][1],
                            aP[kc][2], aP[kc][3], vfr[njp][0], vfr[njp][1]);
                    mma_f16(oacc[2 * njp + 1], aP[kc][0], aP[kc][1],
                            aP[kc][2], aP[kc][3], vfr[njp][2], vfr[njp][3]);
                }
            }
        }
    }

    float l0 = lsum[0], l1 = lsum[1];
    l0 += __shfl_xor_sync(0xffffffffu, l0, 1);
    l0 += __shfl_xor_sync(0xffffffffu, l0, 2);
    l1 += __shfl_xor_sync(0xffffffffu, l1, 1);
    l1 += __shfl_xor_sync(0xffffffffu, l1, 2);
    const float inv0 = 1.0f / l0, inv1 = 1.0f / l1;

    const int r0 = q0 + w * 16 + (lane >> 2);
    __half* dst0 = Ohat + (((size_t)b * SS + r0) * HH + h) * HDIM + (lane & 3) * 2;
    __half* dst1 = dst0 + (size_t)8 * HH * HDIM;
#pragma unroll
    for (int nj = 0; nj < 8; nj++) {
        *(u32*)(dst0 + nj * 8) = pack_f16(oacc[nj][0] * inv0, oacc[nj][1] * inv0);
        *(u32*)(dst1 + nj * 8) = pack_f16(oacc[nj][2] * inv1, oacc[nj][3] * inv1);
    }
}

// ---------------------------------------------------------------------------
// kernel_launch
// ---------------------------------------------------------------------------
extern "C" void kernel_launch(void* const* d_in, const int* in_sizes, int n_in,
                              void* d_out, int out_size) {
    const float* x    = (const float*)d_in[0];
    const float* Wqkv = (const float*)d_in[1];
    const float* Wout = (const float*)d_in[2];
    float* out = (float*)d_out;

    __half *xhat, *ohat, *wqkvT, *woutT;
    __half *qhi, *khi, *vhi;
    cudaGetSymbolAddress((void**)&xhat, g_xhat);
    cudaGetSymbolAddress((void**)&ohat, g_ohat);
    cudaGetSymbolAddress((void**)&wqkvT, g_wqkvT);
    cudaGetSymbolAddress((void**)&woutT, g_woutT);
    cudaGetSymbolAddress((void**)&qhi, g_qhi);
    cudaGetSymbolAddress((void**)&khi, g_khi);
    cudaGetSymbolAddress((void**)&vhi, g_vhi);

    const int M = BB * SS;   // 8192

    // operand prep (+ RoPE table)
    rope_table_kernel<<<SS * 32 / 256, 256>>>();
    convert_f16_kernel<<<M * 128 / 256, 256>>>(x, xhat);
    wtrans_kernel<<<dim3(1536 / 32, 512 / 32), 256>>>(Wqkv, wqkvT, 1536);
    wtrans_kernel<<<dim3(512 / 32, 512 / 32), 256>>>(Wout, woutT, 512);

    // 1) QKV projection + fused table-RoPE/head-split/fp16 epilogue
    cudaFuncSetAttribute(gemm_qkv_kernel, cudaFuncAttributeMaxDynamicSharedMemorySize,
                         GEMM_SMEM);
    gemm_qkv_kernel<<<dim3(1536 / 128, M / 128), 256, GEMM_SMEM>>>(
        xhat, wqkvT, qhi, khi, vhi);

    // 2) flash attention (wq(8), KV tile 128, 2 CTAs/SM)
    cudaFuncSetAttribute(flashmma_kernel, cudaFuncAttributeMaxDynamicSharedMemorySize,
                         FL_SMEM_BYTES);
    flashmma_kernel<<<dim3(SS / 128, BB * HH), 256, FL_SMEM_BYTES>>>(qhi, khi, vhi, ohat);

    // 3) output projection (single-pass fp16, K=512, 2 CTAs/SM)
    cudaFuncSetAttribute(gemm_f16_kernel, cudaFuncAttributeMaxDynamicSharedMemorySize,
                         GEMM_SMEM);
    gemm_f16_kernel<<<dim3(512 / 128, M / 128), 256, GEMM_SMEM>>>(ohat, woutT, out, 512);
}

// round 17
// speedup vs baseline: 1.2047x; 1.1547x over previous
#include <cuda_runtime.h>
#include <cuda_fp16.h>
#include <math.h>

#define BB 2
#define SS 4096
#define DD 512
#define HH 8
#define HDIM 64

typedef unsigned int u32;

// ---------------------------------------------------------------------------
// helpers
// ---------------------------------------------------------------------------
__device__ __forceinline__ u32 pack_f16(float lo, float hi) {
    u32 r;
    asm("cvt.rn.f16x2.f32 %0, %1, %2;" : "=r"(r) : "f"(hi), "f"(lo));
    return r;
}
__device__ __forceinline__ void unpack_f16(u32 p, float& lo, float& hi) {
    __half2 h = *(__half2*)&p;
    float2 f = __half22float2(h);
    lo = f.x; hi = f.y;
}
__device__ __forceinline__ void mma_f16(float* c, u32 a0, u32 a1, u32 a2, u32 a3,
                                        u32 b0, u32 b1) {
    asm("mma.sync.aligned.m16n8k16.row.col.f32.f16.f16.f32 "
        "{%0,%1,%2,%3}, {%4,%5,%6,%7}, {%8,%9}, {%0,%1,%2,%3};"
        : "+f"(c[0]), "+f"(c[1]), "+f"(c[2]), "+f"(c[3])
        : "r"(a0), "r"(a1), "r"(a2), "r"(a3), "r"(b0), "r"(b1));
}
__device__ __forceinline__ void ldsm4(u32* r, u32 addr) {
    asm volatile("ldmatrix.sync.aligned.m8n8.x4.shared.b16 {%0,%1,%2,%3}, [%4];"
        : "=r"(r[0]), "=r"(r[1]), "=r"(r[2]), "=r"(r[3]) : "r"(addr));
}
__device__ __forceinline__ void ldsm4t(u32* r, u32 addr) {
    asm volatile("ldmatrix.sync.aligned.m8n8.x4.trans.shared.b16 {%0,%1,%2,%3}, [%4];"
        : "=r"(r[0]), "=r"(r[1]), "=r"(r[2]), "=r"(r[3]) : "r"(addr));
}
__device__ __forceinline__ void cpa16(u32 dst, const void* src) {
    asm volatile("cp.async.cg.shared.global [%0], [%1], 16;" :: "r"(dst), "l"(src));
}
#define CP_COMMIT() asm volatile("cp.async.commit_group;")
#define CP_WAIT(n)  asm volatile("cp.async.wait_group %0;" :: "n"(n))

#define QSCALE (0.125f * 1.4426950408889634f)

// ---------------------------------------------------------------------------
// Scratch
// ---------------------------------------------------------------------------
__device__ unsigned short g_xhat[(size_t)BB * SS * DD];     // [8192][512]  fp16
__device__ unsigned short g_ohat[(size_t)BB * SS * DD];     // [8192][512]  fp16
__device__ unsigned short g_wqkvT[(size_t)(3 * DD) * DD];   // [1536][512]  fp16
__device__ unsigned short g_woutT[(size_t)DD * DD];         // [512][512]   fp16
__device__ unsigned short g_qhi[(size_t)BB * HH * SS * HDIM];
__device__ unsigned short g_khi[(size_t)BB * HH * SS * HDIM];
__device__ unsigned short g_vhi[(size_t)BB * HH * SS * HDIM];
__device__ float2 g_rope[(size_t)SS * 32];                  // [4096][32] (cos,sin)

// ---------------------------------------------------------------------------
// Fused prep kernel: one launch, blockIdx-range dispatch.
//   [0, 512)       rope table (bitwise-same powf/sincosf pipeline)
//   [512, 4608)    x f32 -> fp16 convert
//   [4608, 5376)   Wqkv transpose (N=1536): 16 x 48 tiles of 32x32
//   [5376, 5632)   Wout transpose (N=512):  16 x 16 tiles of 32x32
// ---------------------------------------------------------------------------
__device__ __forceinline__ void wtrans_body(const float* __restrict__ B,
                                            __half* __restrict__ Bt, int N,
                                            int k0, int n0, int t,
                                            __half shi[32][36]) {
    {
        int kk = t >> 3, n4 = (t & 7) * 4;
        float4 v = *(const float4*)(B + (size_t)(k0 + kk) * N + n0 + n4);
        shi[kk][n4 + 0] = __float2half_rn(v.x);
        shi[kk][n4 + 1] = __float2half_rn(v.y);
        shi[kk][n4 + 2] = __float2half_rn(v.z);
        shi[kk][n4 + 3] = __float2half_rn(v.w);
    }
    __syncthreads();
    {
        int nn = t >> 3, k4 = (t & 7) * 4;
        __half2 h01, h23;
        h01.x = shi[k4 + 0][nn]; h01.y = shi[k4 + 1][nn];
        h23.x = shi[k4 + 2][nn]; h23.y = shi[k4 + 3][nn];
        uint2 hw = make_uint2(*(u32*)&h01, *(u32*)&h23);
        *(uint2*)(Bt + (size_t)(n0 + nn) * DD + k0 + k4) = hw;
    }
}

__global__ __launch_bounds__(256)
void prep_kernel(const float* __restrict__ x, __half* __restrict__ xhat,
                 const float* __restrict__ Wqkv, __half* __restrict__ wqkvT,
                 const float* __restrict__ Wout, __half* __restrict__ woutT) {
    __shared__ __half shi[32][36];
    const int blk = blockIdx.x;
    const int t = threadIdx.x;

    if (blk < 512) {
        // rope table
        int idx = blk * 256 + t;
        int i = idx & 31, s = idx >> 5;
        float invf = 1.0f / powf(10000.0f, (float)i * (1.0f / 32.0f));
        float sn, cs;
        sincosf((float)s * invf, &sn, &cs);
        g_rope[idx] = make_float2(cs, sn);
    } else if (blk < 4608) {
        // x -> fp16
        int idx = (blk - 512) * 256 + t;
        float4 tv = *(const float4*)(x + (size_t)idx * 4);
        uint2 hw = make_uint2(pack_f16(tv.x, tv.y), pack_f16(tv.z, tv.w));
        *(uint2*)(xhat + (size_t)idx * 4) = hw;
    } else if (blk < 5376) {
        int b = blk - 4608;                   // 16 rows x 48 cols
        wtrans_body(Wqkv, wqkvT, 1536, (b / 48) * 32, (b % 48) * 32, t, shi);
    } else {
        int b = blk - 5376;                   // 16 x 16
        wtrans_body(Wout, woutT, 512, (b / 16) * 32, (b % 16) * 32, t, shi);
    }
}

// ---------------------------------------------------------------------------
// GEMM mainloop (shared): BK=64, 2-stage ring.
// ---------------------------------------------------------------------------
#define GLDK 72
#define GOPB (128 * GLDK * 2)        // 18432 B per operand-stage
#define GEMM_SMEM (4 * GOPB)         // 73728 B

__device__ __forceinline__ void gemm_mainloop(
    const __half* __restrict__ A, const __half* __restrict__ Bt,
    u32 base, int bm, int bn, int tid, float acc[4][4][4]) {
    const int lane = tid & 31, w = tid >> 5;
    const int wm = w >> 2, wn = w & 3;
    const int lrow = tid >> 3;
    const int lc8 = (tid & 7) * 8;

#pragma unroll
    for (int mi = 0; mi < 4; mi++)
#pragma unroll
        for (int ni = 0; ni < 4; ni++)
#pragma unroll
            for (int e = 0; e < 4; e++) acc[mi][ni][e] = 0.f;

    const int NKT = DD / 64;   // 8

    {
        const __half* Ag = A + (size_t)bm * DD;
        const __half* Bg = Bt + (size_t)bn * DD;
#pragma unroll
        for (int i = 0; i < 4; i++) {
            int row = lrow + i * 32;
            u32 off = (u32)((row * GLDK + lc8) * 2);
            cpa16(base + off, Ag + (size_t)row * DD + lc8);
            cpa16(base + 2 * GOPB + off, Bg + (size_t)row * DD + lc8);
        }
        CP_COMMIT();
    }

#pragma unroll 1
    for (int kt = 0; kt < NKT; kt++) {
        CP_WAIT(0);
        __syncthreads();

        if (kt + 1 < NKT) {
            const int s = (kt + 1) & 1;
            const __half* Ag = A + (size_t)bm * DD + (kt + 1) * 64;
            const __half* Bg = Bt + (size_t)bn * DD + (kt + 1) * 64;
#pragma unroll
            for (int i = 0; i < 4; i++) {
                int row = lrow + i * 32;
                u32 off = (u32)((row * GLDK + lc8) * 2);
                cpa16(base + s * GOPB + off, Ag + (size_t)row * DD + lc8);
                cpa16(base + 2 * GOPB + s * GOPB + off, Bg + (size_t)row * DD + lc8);
            }
            CP_COMMIT();
        }

        const int s = kt & 1;
        const u32 Ab = base + s * GOPB;
        const u32 Bb = base + 2 * GOPB + s * GOPB;
        const int lr = lane & 15, lc = (lane >> 4) * 8;
#pragma unroll
        for (int ks = 0; ks < 4; ks++) {
            const int col = ks * 16 + lc;
            u32 a[4][4], b[4][2];
#pragma unroll
            for (int mi = 0; mi < 4; mi++)
                ldsm4(a[mi], Ab + (u32)(((wm * 64 + mi * 16 + lr) * GLDK + col) * 2));
#pragma unroll
            for (int nip = 0; nip < 2; nip++) {
                u32 t[4];
                ldsm4(t, Bb + (u32)(((wn * 32 + nip * 16 + lr) * GLDK + col) * 2));
                b[2 * nip][0] = t[0]; b[2 * nip + 1][0] = t[1];
                b[2 * nip][1] = t[2]; b[2 * nip + 1][1] = t[3];
            }
#pragma unroll
            for (int mi = 0; mi < 4; mi++)
#pragma unroll
                for (int ni = 0; ni < 4; ni++)
                    mma_f16(acc[mi][ni], a[mi][0], a[mi][1], a[mi][2], a[mi][3],
                            b[ni][0], b[ni][1]);
        }
    }
}

// ---------------------------------------------------------------------------
// out-projection GEMM: f32 C output (final result)
// ---------------------------------------------------------------------------
__global__ __launch_bounds__(256, 2)
void gemm_f16_kernel(const __half* __restrict__ A,
                     const __half* __restrict__ Bt,
                     float* __restrict__ C, int N) {
    extern __shared__ char gsm[];
    const u32 base = (u32)__cvta_generic_to_shared(gsm);
    const int tid = threadIdx.x;
    const int lane = tid & 31, w = tid >> 5;
    const int wm = w >> 2, wn = w & 3;
    const int bm = blockIdx.y * 128, bn = blockIdx.x * 128;

    float acc[4][4][4];
    gemm_mainloop(A, Bt, base, bm, bn, tid, acc);

#pragma unroll
    for (int mi = 0; mi < 4; mi++) {
        int r = bm + wm * 64 + mi * 16 + (lane >> 2);
#pragma unroll
        for (int ni = 0; ni < 4; ni++) {
            int c = bn + wn * 32 + ni * 8 + (lane & 3) * 2;
            *(float2*)&C[(size_t)r * N + c] = make_float2(acc[mi][ni][0], acc[mi][ni][1]);
            *(float2*)&C[(size_t)(r + 8) * N + c] = make_float2(acc[mi][ni][2], acc[mi][ni][3]);
        }
    }
}

// ---------------------------------------------------------------------------
// QKV GEMM with fused table-RoPE + head-split + fp16 epilogue.
// ---------------------------------------------------------------------------
#define CF_LD 132

__global__ __launch_bounds__(256, 2)
void gemm_qkv_kernel(const __half* __restrict__ A,
                     const __half* __restrict__ Bt,
                     __half* __restrict__ Qhi, __half* __restrict__ Khi,
                     __half* __restrict__ Vhi) {
    extern __shared__ char gsm[];
    const u32 base = (u32)__cvta_generic_to_shared(gsm);
    float* Cf = (float*)gsm;                 // [128][132] = 67584 B (< 73728)
    const int tid = threadIdx.x;
    const int lane = tid & 31, w = tid >> 5;
    const int wm = w >> 2, wn = w & 3;
    const int bm = blockIdx.y * 128, bn = blockIdx.x * 128;

    float acc[4][4][4];
    gemm_mainloop(A, Bt, base, bm, bn, tid, acc);

    __syncthreads();
#pragma unroll
    for (int mi = 0; mi < 4; mi++) {
        int r = wm * 64 + mi * 16 + (lane >> 2);
#pragma unroll
        for (int ni = 0; ni < 4; ni++) {
            int c = wn * 32 + ni * 8 + (lane & 3) * 2;
            *(float2*)&Cf[r * CF_LD + c] = make_float2(acc[mi][ni][0], acc[mi][ni][1]);
            *(float2*)&Cf[(r + 8) * CF_LD + c] = make_float2(acc[mi][ni][2], acc[mi][ni][3]);
        }
    }
    __syncthreads();

    const int region = bn >> 9;              // bn / 512
    const int h0 = (bn & 511) >> 6;
    const int pc = tid & 31;
    const int hh = pc >> 4;
    const int ii = (pc & 15) * 2;
    const int hq = h0 + hh;

#pragma unroll 1
    for (int row = tid >> 5; row < 128; row += 8) {
        const int gr = bm + row;
        const int s = gr & (SS - 1);
        const int b = gr >> 12;
        const float2 v1 = *(const float2*)&Cf[row * CF_LD + hh * 64 + ii];
        const float2 v2 = *(const float2*)&Cf[row * CF_LD + hh * 64 + ii + 32];
        const size_t orow = ((size_t)(b * HH + hq) * SS + s) * HDIM;

        if (region == 2) {
            *(u32*)&Vhi[orow + ii]      = pack_f16(v1.x, v1.y);
            *(u32*)&Vhi[orow + ii + 32] = pack_f16(v2.x, v2.y);
        } else {
            const float2 ta = g_rope[s * 32 + ii];
            const float2 tb = g_rope[s * 32 + ii + 1];
            float r1a = v1.x * ta.x - v2.x * ta.y;
            float r1b = v1.y * tb.x - v2.y * tb.y;
            float r2a = v2.x * ta.x + v1.x * ta.y;
            float r2b = v2.y * tb.x + v1.y * tb.y;
            if (region == 0) {
                r1a *= QSCALE; r1b *= QSCALE; r2a *= QSCALE; r2b *= QSCALE;
                *(u32*)&Qhi[orow + ii]      = pack_f16(r1a, r1b);
                *(u32*)&Qhi[orow + ii + 32] = pack_f16(r2a, r2b);
            } else {
                *(u32*)&Khi[orow + ii]      = pack_f16(r1a, r1b);
                *(u32*)&Khi[orow + ii + 32] = pack_f16(r2a, r2b);
            }
        }
    }
}

// ---------------------------------------------------------------------------
// Flash attention fp16, wq(8) layout, KV tile 128, 2 CTAs/SM.
// Q-TILE PAIRING: CTA x processes q-tiles x and 31-x sequentially ->
// uniform 33 work-units per CTA, 256 CTAs = single wave.
// ---------------------------------------------------------------------------
#define FL_LD 72
#define FL_QSZ   (128 * FL_LD * 2)
#define FL_KSTG  (128 * FL_LD * 2)
#define FL_HALF  (64 * FL_LD * 2)
#define FL_SMEM_BYTES (FL_QSZ + 2 * FL_KSTG + 2 * FL_KSTG)   // 92160

__global__ __launch_bounds__(256, 2)
void flashmma_kernel(const __half* __restrict__ Qhi,
                     const __half* __restrict__ Khi, const __half* __restrict__ Vhi,
                     __half* __restrict__ Ohat) {
    extern __shared__ char smraw[];
    const u32 smb = (u32)__cvta_generic_to_shared(smraw);
    const u32 Qb = smb;
    const u32 Kb = smb + FL_QSZ;
    const u32 Vb = Kb + 2 * FL_KSTG;

    const int tid = threadIdx.x, lane = tid & 31, w = tid >> 5;
    const int bh = blockIdx.y;
    const int b = bh >> 3, h = bh & 7;
    const size_t koff = (size_t)bh * SS * HDIM;

    const int lrow = tid >> 3;
    const int lc8 = (tid & 7) * 8;
    const int lr = lane & 15, lc = (lane >> 4) * 8;
    const int NQT = SS / 128;               // 32

#pragma unroll 1
    for (int phase = 0; phase < 2; phase++) {
        const int qt = phase == 0 ? (int)blockIdx.x : (NQT - 1 - (int)blockIdx.x);
        const int q0 = qt * 128;
        const size_t qoff = ((size_t)bh * SS + q0) * HDIM;

        // guard K/V/Q buffer reuse against phase-0 readers
        __syncthreads();

        // ---- issue Q + KV tile 0 (128 rows) as one group ----
#pragma unroll
        for (int i = 0; i < 4; i++) {
            int row = lrow + i * 32;
            u32 off = (u32)((row * FL_LD + lc8) * 2);
            cpa16(Qb + off, Qhi + qoff + (size_t)row * HDIM + lc8);
            cpa16(Kb + off, Khi + koff + (size_t)row * HDIM + lc8);
            cpa16(Vb + off, Vhi + koff + (size_t)row * HDIM + lc8);
        }
        CP_COMMIT();

        float oacc[8][4];
#pragma unroll
        for (int nj = 0; nj < 8; nj++)
#pragma unroll
            for (int e = 0; e < 4; e++) oacc[nj][e] = 0.f;
        float lsum[2] = {0.f, 0.f};

        u32 aq[4][4];

        const int jmax = qt;
#pragma unroll 1
        for (int j = 0; j <= jmax; j++) {
            CP_WAIT(0);
            __syncthreads();

            if (j == 0) {
#pragma unroll
                for (int ks = 0; ks < 4; ks++)
                    ldsm4(aq[ks],
                          Qb + (u32)(((w * 16 + lr) * FL_LD + ks * 16 + lc) * 2));
            }

            if (j < jmax) {
                const int s = (j + 1) & 1;
                const size_t kvg = koff + (size_t)((j + 1) * 128) * HDIM;
#pragma unroll
                for (int i = 0; i < 4; i++) {
                    int row = lrow + i * 32;
                    u32 off = (u32)((row * FL_LD + lc8) * 2);
                    cpa16(Kb + s * FL_KSTG + off, Khi + kvg + (size_t)row * HDIM + lc8);
                    cpa16(Vb + s * FL_KSTG + off, Vhi + kvg + (size_t)row * HDIM + lc8);
                }
                CP_COMMIT();
            }

            const int s = j & 1;
            const int rg = q0 + w * 16 + (lane >> 2);

#pragma unroll
            for (int half = 0; half < 2; half++) {
                const u32 khb = Kb + s * FL_KSTG + half * FL_HALF;
                const u32 vhb = Vb + s * FL_KSTG + half * FL_HALF;
                const int kv0 = j * 128 + half * 64;

                float sacc[8][4];
#pragma unroll
                for (int ni = 0; ni < 8; ni++)
#pragma unroll
                    for (int e = 0; e < 4; e++) sacc[ni][e] = 0.f;
#pragma unroll
                for (int ks = 0; ks < 4; ks++) {
                    const int col = ks * 16 + lc;
                    u32 bhr[8][2];
#pragma unroll
                    for (int nip = 0; nip < 4; nip++) {
                        u32 ro = (u32)(((nip * 16 + lr) * FL_LD + col) * 2);
                        u32 t[4];
                        ldsm4(t, khb + ro);
                        bhr[2 * nip][0] = t[0]; bhr[2 * nip + 1][0] = t[1];
                        bhr[2 * nip][1] = t[2]; bhr[2 * nip + 1][1] = t[3];
                    }
#pragma unroll
                    for (int ni = 0; ni < 8; ni++)
                        mma_f16(sacc[ni], aq[ks][0], aq[ks][1], aq[ks][2], aq[ks][3],
                                bhr[ni][0], bhr[ni][1]);
                }

                const bool diag = (kv0 + 63 > q0);
                u32 aP[4][4];
#pragma unroll
                for (int ni = 0; ni < 8; ni++) {
                    const int cg = kv0 + ni * 8 + (lane & 3) * 2;
                    float e0 = exp2f(sacc[ni][0]);
                    float e1 = exp2f(sacc[ni][1]);
                    float e2 = exp2f(sacc[ni][2]);
                    float e3 = exp2f(sacc[ni][3]);
                    if (diag) {
                        if (cg > rg) e0 = 0.f;
                        if (cg + 1 > rg) e1 = 0.f;
                        if (cg > rg + 8) e2 = 0.f;
                        if (cg + 1 > rg + 8) e3 = 0.f;
                    }
                    u32 p01 = pack_f16(e0, e1);
                    u32 p23 = pack_f16(e2, e3);
                    float f0, f1, f2, f3;
                    unpack_f16(p01, f0, f1);
                    unpack_f16(p23, f2, f3);
                    lsum[0] += f0 + f1;
                    lsum[1] += f2 + f3;
                    const int kc = ni >> 1, hf = (ni & 1) * 2;
                    aP[kc][hf]     = p01;
                    aP[kc][hf + 1] = p23;
                }

#pragma unroll
                for (int kc = 0; kc < 4; kc++) {
                    const u32 rowoff = (u32)((kc * 16 + lr) * FL_LD + lc);
                    u32 vfr[4][4];
#pragma unroll
                    for (int njp = 0; njp < 4; njp++)
                        ldsm4t(vfr[njp], vhb + (rowoff + (u32)(njp * 16)) * 2);
#pragma unroll
                    for (int njp = 0; njp < 4; njp++) {
                        mma_f16(oacc[2 * njp], aP[kc][0], aP[kc][1],
                                aP[kc][2], aP[kc][3], vfr[njp][0], vfr[njp][1]);
                        mma_f16(oacc[2 * njp + 1], aP[kc][0], aP[kc][1],
                                aP[kc][2], aP[kc][3], vfr[njp][2], vfr[njp][3]);
                    }
                }
            }
        }

        float l0 = lsum[0], l1 = lsum[1];
        l0 += __shfl_xor_sync(0xffffffffu, l0, 1);
        l0 += __shfl_xor_sync(0xffffffffu, l0, 2);
        l1 += __shfl_xor_sync(0xffffffffu, l1, 1);
        l1 += __shfl_xor_sync(0xffffffffu, l1, 2);
        const float inv0 = 1.0f / l0, inv1 = 1.0f / l1;

        const int r0 = q0 + w * 16 + (lane >> 2);
        __half* dst0 = Ohat + (((size_t)b * SS + r0) * HH + h) * HDIM + (lane & 3) * 2;
        __half* dst1 = dst0 + (size_t)8 * HH * HDIM;
#pragma unroll
        for (int nj = 0; nj < 8; nj++) {
            *(u32*)(dst0 + nj * 8) = pack_f16(oacc[nj][0] * inv0, oacc[nj][1] * inv0);
            *(u32*)(dst1 + nj * 8) = pack_f16(oacc[nj][2] * inv1, oacc[nj][3] * inv1);
        }
    }
}

// ---------------------------------------------------------------------------
// kernel_launch
// ---------------------------------------------------------------------------
extern "C" void kernel_launch(void* const* d_in, const int* in_sizes, int n_in,
                              void* d_out, int out_size) {
    const float* x    = (const float*)d_in[0];
    const float* Wqkv = (const float*)d_in[1];
    const float* Wout = (const float*)d_in[2];
    float* out = (float*)d_out;

    __half *xhat, *ohat, *wqkvT, *woutT;
    __half *qhi, *khi, *vhi;
    cudaGetSymbolAddress((void**)&xhat, g_xhat);
    cudaGetSymbolAddress((void**)&ohat, g_ohat);
    cudaGetSymbolAddress((void**)&wqkvT, g_wqkvT);
    cudaGetSymbolAddress((void**)&woutT, g_woutT);
    cudaGetSymbolAddress((void**)&qhi, g_qhi);
    cudaGetSymbolAddress((void**)&khi, g_khi);
    cudaGetSymbolAddress((void**)&vhi, g_vhi);

    const int M = BB * SS;   // 8192

    // 0) fused prep: rope table + x convert + both weight transposes
    prep_kernel<<<5632, 256>>>(x, xhat, Wqkv, wqkvT, Wout, woutT);

    // 1) QKV projection + fused table-RoPE/head-split/fp16 epilogue
    cudaFuncSetAttribute(gemm_qkv_kernel, cudaFuncAttributeMaxDynamicSharedMemorySize,
                         GEMM_SMEM);
    gemm_qkv_kernel<<<dim3(1536 / 128, M / 128), 256, GEMM_SMEM>>>(
        xhat, wqkvT, qhi, khi, vhi);

    // 2) flash attention (wq(8), KV tile 128, paired q-tiles, single wave)
    cudaFuncSetAttribute(flashmma_kernel, cudaFuncAttributeMaxDynamicSharedMemorySize,
                         FL_SMEM_BYTES);
    flashmma_kernel<<<dim3(SS / 256, BB * HH), 256, FL_SMEM_BYTES>>>(qhi, khi, vhi, ohat);

    // 3) output projection (single-pass fp16, K=512, 2 CTAs/SM)
    cudaFuncSetAttribute(gemm_f16_kernel, cudaFuncAttributeMaxDynamicSharedMemorySize,
                         GEMM_SMEM);
    gemm_f16_kernel<<<dim3(512 / 128, M / 128), 256, GEMM_SMEM>>>(ohat, woutT, out, 512);
}